// round 7
// baseline (speedup 1.0000x reference)
#include <cuda_runtime.h>
#include <cuda_fp16.h>
#include <cstdint>

#define QT (16*6*64*49*32)            // 9,633,792 elements per q/k/v tensor

__device__ __half g_xh[50176 * 192];  // rolled x, fp16, token-major
__device__ __half g_wh[576 * 192];    // wqkv^T [n][k] fp16
__device__ __half g_woh[192 * 192];   // wout^T [n][k] fp16
__device__ __half g_qkvh[3u * QT];    // q|k|v fp16, window layout [b,h,win,49,32]
__device__ __half g_atth[QT];         // attention out fp16, window layout

// ---------------- helpers ----------------
__device__ __forceinline__ void mma16(float* c, const uint32_t* a, const uint32_t* b) {
    asm volatile("mma.sync.aligned.m16n8k16.row.col.f32.f16.f16.f32 "
        "{%0,%1,%2,%3}, {%4,%5,%6,%7}, {%8,%9}, {%0,%1,%2,%3};\n"
        : "+f"(c[0]), "+f"(c[1]), "+f"(c[2]), "+f"(c[3])
        : "r"(a[0]), "r"(a[1]), "r"(a[2]), "r"(a[3]), "r"(b[0]), "r"(b[1]));
}
__device__ __forceinline__ void ldsm4(uint32_t* r, uint32_t addr) {
    asm volatile("ldmatrix.sync.aligned.m8n8.x4.shared.b16 {%0,%1,%2,%3}, [%4];"
        : "=r"(r[0]), "=r"(r[1]), "=r"(r[2]), "=r"(r[3]) : "r"(addr));
}
__device__ __forceinline__ void cpa16(uint32_t s, const void* g) {
    asm volatile("cp.async.cg.shared.global [%0], [%1], 16;" :: "r"(s), "l"(g));
}
#define CP_COMMIT() asm volatile("cp.async.commit_group;")
#define CP_WAIT1()  asm volatile("cp.async.wait_group 1;")
#define CP_WAIT0()  asm volatile("cp.async.wait_group 0;")
__device__ __forceinline__ uint32_t smem_u32(const void* p) {
    uint32_t a;
    asm("{ .reg .u64 t; cvta.to.shared.u64 t, %1; cvt.u32.u64 %0, t; }" : "=r"(a) : "l"(p));
    return a;
}
__device__ __forceinline__ uint32_t h2u(__half2 h) { return *reinterpret_cast<uint32_t*>(&h); }

// ================= prep kernels =================
__global__ __launch_bounds__(256) void prep_x(const float* __restrict__ x) {
    int i = blockIdx.x * 256 + threadIdx.x;
    int e = i * 4;
    int t = e / 192, c = e - t * 192;
    int b = t / 3136; int r = t - b * 3136;
    int y = r / 56, xx = r - y * 56;
    int ys = y + 3;  if (ys >= 56) ys -= 56;
    int xs = xx + 3; if (xs >= 56) xs -= 56;
    float4 v = *(const float4*)(x + ((b * 56 + ys) * 56 + xs) * 192 + c);
    *(__half2*)(g_xh + e)     = __floats2half2_rn(v.x, v.y);
    *(__half2*)(g_xh + e + 2) = __floats2half2_rn(v.z, v.w);
}
__global__ __launch_bounds__(256) void prep_w(const float* __restrict__ w) {
    int i = blockIdx.x * 256 + threadIdx.x;
    int e = i * 4;
    int n = e / 192, k = e - n * 192;
#pragma unroll
    for (int j = 0; j < 4; j++)
        g_wh[e + j] = __float2half_rn(w[(k + j) * 576 + n]);
}
__global__ __launch_bounds__(256) void prep_wo(const float* __restrict__ w) {
    int i = blockIdx.x * 256 + threadIdx.x;
    int e = i * 4;
    int n = e / 192, k = e - n * 192;
#pragma unroll
    for (int j = 0; j < 4; j++)
        g_woh[e + j] = __float2half_rn(w[(k + j) * 192 + n]);
}

// ============ fp16 GEMM: BM=128, BN=96, BK=32, 128 threads (4 warps 2x2) ============
#define LDA 40

// ================= Kernel 1: QKV GEMM =================
__global__ __launch_bounds__(128, 3) void qkv_gemm(void)
{
    __shared__ __align__(16) __half As[2][128 * LDA];
    __shared__ __align__(16) __half Bs[2][96 * LDA];

    const int tid  = threadIdx.x;
    const int warp = tid >> 5, lane = tid & 31;
    const int wm   = warp & 1, wn = warp >> 1;
    const int g    = lane >> 2, tg = lane & 3;
    const int bm   = blockIdx.x * 128;
    const int nb   = blockIdx.y;

    const __half* ap = g_xh + (size_t)(bm + tid) * 192;
    const int bn = tid >> 2, bq = tid & 3;

    uint32_t a_s[2], b_s[2];
    a_s[0] = smem_u32(As[0]); a_s[1] = smem_u32(As[1]);
    b_s[0] = smem_u32(Bs[0]); b_s[1] = smem_u32(Bs[1]);

    // ldmatrix per-lane offsets (bytes)
    const int lr = lane & 7, lm = (lane >> 3) & 1, lk = lane >> 4;
    const uint32_t aoff = (uint32_t)((wm * 64 + lr + lm * 8) * LDA + lk * 8) * 2;
    const uint32_t boff = (uint32_t)((wn * 48 + lr + lm * 8) * LDA + lk * 8) * 2;

#define LD_CHUNK(cc, ss) do { \
        uint32_t ad = a_s[ss] + (uint32_t)(tid * LDA) * 2; \
        const __half* asrc = ap + (cc) * 32; \
        cpa16(ad + 0,  asrc + 0);  cpa16(ad + 16, asrc + 8); \
        cpa16(ad + 32, asrc + 16); cpa16(ad + 48, asrc + 24); \
        _Pragma("unroll") \
        for (int ii = 0; ii < 3; ii++) { \
            int n = bn + ii * 32; \
            cpa16(b_s[ss] + (uint32_t)(n * LDA + bq * 8) * 2, \
                  g_wh + (size_t)(nb * 96 + n) * 192 + (cc) * 32 + bq * 8); \
        } \
        CP_COMMIT(); } while (0)

    float c[4][6][4] = {};
    LD_CHUNK(0, 0);

#pragma unroll 1
    for (int ch = 0; ch < 6; ch++) {
        const int s = ch & 1;
        if (ch < 5) { LD_CHUNK(ch + 1, s ^ 1); CP_WAIT1(); }
        else        { CP_WAIT0(); }
        __syncthreads();

#pragma unroll
        for (int kk = 0; kk < 32; kk += 16) {
            uint32_t af[4][4], bf[6][2];
#pragma unroll
            for (int mi = 0; mi < 4; mi++)
                ldsm4(af[mi], a_s[s] + aoff + (uint32_t)(mi * 16 * LDA + kk) * 2);
#pragma unroll
            for (int nj = 0; nj < 3; nj++) {
                uint32_t r[4];
                ldsm4(r, b_s[s] + boff + (uint32_t)(nj * 16 * LDA + kk) * 2);
                bf[2 * nj][0] = r[0]; bf[2 * nj + 1][0] = r[1];
                bf[2 * nj][1] = r[2]; bf[2 * nj + 1][1] = r[3];
            }
#pragma unroll
            for (int mi = 0; mi < 4; mi++)
#pragma unroll
                for (int ni = 0; ni < 6; ni++)
                    mma16(c[mi][ni], af[mi], bf[ni]);
        }
        __syncthreads();
    }

    const int t = nb >> 1;
    __half* qb = g_qkvh + (size_t)t * QT;
#pragma unroll
    for (int mi = 0; mi < 4; mi++) {
#pragma unroll
        for (int half = 0; half < 2; half++) {
            int r = bm + wm * 64 + mi * 16 + g + half * 8;
            int b = r / 3136; int rr = r - b * 3136;
            int y = rr / 56, xx = rr - y * 56;
            int wv = (y / 7) * 8 + (xx / 7);
            int tk = (y % 7) * 7 + (xx % 7);
            __half* base = qb + b * 602112 + wv * 1568 + tk * 32;
#pragma unroll
            for (int ni = 0; ni < 6; ni++) {
                int cp = nb * 96 + wn * 48 + ni * 8 + tg * 2;
                int cc = cp - t * 192;
                int h = cc >> 5, d = cc & 31;
                *(__half2*)(base + h * 100352 + d) =
                    __floats2half2_rn(c[mi][ni][half * 2], c[mi][ni][half * 2 + 1]);
            }
        }
    }
}

// ================= Kernel 2: HMMA attention =================
#define LDQ 40   // halves per row of Qs/Ks
#define LDV 72   // halves per row of Vt

__global__ __launch_bounds__(128) void attn_hmma(const float* __restrict__ pe)
{
    __shared__ __align__(16) __half Qs[64 * LDQ];
    __shared__ __align__(16) __half Ks[64 * LDQ];
    __shared__ __align__(16) __half Vt[32 * LDV];
    __shared__ float PE[169];

    const int tid = threadIdx.x;
    const int w = tid >> 5, lane = tid & 31;
    const int g = lane >> 2, t = lane & 3;
    const int bx = blockIdx.x;
    const int wv = bx & 63;
    const int wy = wv >> 3, wx = wv & 7;
    const bool mrow = (wy == 7), mcol = (wx == 7);

    const __half2* qg = (const __half2*)(g_qkvh + (size_t)bx * 1568);
    const __half2* kg = (const __half2*)(g_qkvh + (size_t)QT + (size_t)bx * 1568);
    const __half2* vg = (const __half2*)(g_qkvh + 2 * (size_t)QT + (size_t)bx * 1568);

    const __half2 z2 = __floats2half2_rn(0.f, 0.f);
    for (int p = tid; p < 1280; p += 128) {
        int i = p / 20, dp = p - i * 20;
        __half2 qv = z2, kv = z2;
        if (dp < 16 && i < 49) { qv = qg[i * 16 + dp]; kv = kg[i * 16 + dp]; }
        *(__half2*)(Qs + i * LDQ + dp * 2) = qv;
        *(__half2*)(Ks + i * LDQ + dp * 2) = kv;
    }
    for (int p = tid; p < 784; p += 128) {
        int i = p >> 4, dp = p & 15;
        __half2 v = vg[p];
        Vt[(2 * dp) * LDV + i]     = __low2half(v);
        Vt[(2 * dp + 1) * LDV + i] = __high2half(v);
    }
    for (int p = tid; p < 480; p += 128) {
        int d = p / 15, c = 49 + (p - d * 15);
        Vt[d * LDV + c] = __float2half_rn(0.f);
    }
    for (int p = tid; p < 169; p += 128) PE[p] = pe[p];
    __syncthreads();

    const uint32_t qs_b = smem_u32(Qs), ks_b = smem_u32(Ks), vt_b = smem_u32(Vt);
    const int lr = lane & 7, lm = (lane >> 3) & 1, lk = lane >> 4;
    const uint32_t qoff = (uint32_t)((w * 16 + lr + lm * 8) * LDQ + lk * 8) * 2;
    const uint32_t koff = (uint32_t)((lr + lm * 8) * LDQ + lk * 8) * 2;
    const uint32_t voff = (uint32_t)((lr + lm * 8) * LDV + lk * 8) * 2;

    // ---- S = Q K^T ----
    float S[8][4] = {};
#pragma unroll
    for (int kk = 0; kk < 32; kk += 16) {
        uint32_t a[4];
        ldsm4(a, qs_b + qoff + (uint32_t)kk * 2);
#pragma unroll
        for (int np = 0; np < 4; np++) {
            uint32_t r[4];
            ldsm4(r, ks_b + koff + (uint32_t)(np * 16 * LDQ + kk) * 2);
            uint32_t b0[2] = { r[0], r[2] };
            uint32_t b1[2] = { r[1], r[3] };
            mma16(S[2 * np], a, b0);
            mma16(S[2 * np + 1], a, b1);
        }
    }

    // ---- bias + mask + softmax ----
    const float scale = 0.17677669529663687f;
#pragma unroll
    for (int rw = 0; rw < 2; rw++) {
        int i = w * 16 + g + rw * 8;
        int ic = (i < 49) ? i : 48;
        int iy = ic / 7, ix = ic - iy * 7;
        float mx = -1e30f;
#pragma unroll
        for (int n = 0; n < 8; n++) {
#pragma unroll
            for (int e = 0; e < 2; e++) {
                int j = n * 8 + 2 * t + e;
                float v;
                if (j < 49) {
                    int jy = j / 7, jx = j - jy * 7;
                    v = S[n][rw * 2 + e] * scale + PE[(jy - iy + 6) * 13 + (jx - ix + 6)];
                    if (mrow && ((iy >= 4) != (jy >= 4))) v -= 1e9f;
                    if (mcol && ((ix >= 4) != (jx >= 4))) v -= 1e9f;
                } else {
                    v = -1e9f;
                }
                S[n][rw * 2 + e] = v;
                mx = fmaxf(mx, v);
            }
        }
        mx = fmaxf(mx, __shfl_xor_sync(0xffffffffu, mx, 1));
        mx = fmaxf(mx, __shfl_xor_sync(0xffffffffu, mx, 2));
        float sm = 0.f;
#pragma unroll
        for (int n = 0; n < 8; n++) {
#pragma unroll
            for (int e = 0; e < 2; e++) {
                float ex = __expf(S[n][rw * 2 + e] - mx);
                S[n][rw * 2 + e] = ex;
                sm += ex;
            }
        }
        sm += __shfl_xor_sync(0xffffffffu, sm, 1);
        sm += __shfl_xor_sync(0xffffffffu, sm, 2);
        float inv = 1.f / sm;
#pragma unroll
        for (int n = 0; n < 8; n++) {
            S[n][rw * 2 + 0] *= inv;
            S[n][rw * 2 + 1] *= inv;
        }
    }

    // ---- repack P into A-fragments ----
    uint32_t Pa[4][4];
#pragma unroll
    for (int c = 0; c < 4; c++) {
        Pa[c][0] = h2u(__floats2half2_rn(S[2 * c][0],     S[2 * c][1]));
        Pa[c][1] = h2u(__floats2half2_rn(S[2 * c][2],     S[2 * c][3]));
        Pa[c][2] = h2u(__floats2half2_rn(S[2 * c + 1][0], S[2 * c + 1][1]));
        Pa[c][3] = h2u(__floats2half2_rn(S[2 * c + 1][2], S[2 * c + 1][3]));
    }

    // ---- O = P V ----
    float O[4][4] = {};
#pragma unroll
    for (int c = 0; c < 4; c++) {
#pragma unroll
        for (int np = 0; np < 2; np++) {
            uint32_t r[4];
            ldsm4(r, vt_b + voff + (uint32_t)(np * 16 * LDV + c * 16) * 2);
            uint32_t b0[2] = { r[0], r[2] };
            uint32_t b1[2] = { r[1], r[3] };
            mma16(O[2 * np], Pa[c], b0);
            mma16(O[2 * np + 1], Pa[c], b1);
        }
    }

    // ---- store fp16 ----
    __half* og = g_atth + (size_t)bx * 1568;
#pragma unroll
    for (int rw = 0; rw < 2; rw++) {
        int i = w * 16 + g + rw * 8;
        if (i < 49) {
#pragma unroll
            for (int nt = 0; nt < 4; nt++)
                *(__half2*)(og + i * 32 + nt * 8 + 2 * t) =
                    __floats2half2_rn(O[nt][rw * 2], O[nt][rw * 2 + 1]);
        }
    }
}

// ================= Kernel 3: out-proj GEMM + inverse roll =================
__global__ __launch_bounds__(128, 3) void proj_gemm(
    const float* __restrict__ bout, float* __restrict__ out)
{
    __shared__ __align__(16) __half As[2][128 * LDA];
    __shared__ __align__(16) __half Bs[2][96 * LDA];

    const int tid  = threadIdx.x;
    const int warp = tid >> 5, lane = tid & 31;
    const int wm   = warp & 1, wn = warp >> 1;
    const int g    = lane >> 2, tg = lane & 3;
    const int bm   = blockIdx.x * 128;
    const int nb   = blockIdx.y;

    const __half* abase;
    {
        int row = bm + tid;
        int b = row / 3136; int r = row - b * 3136;
        int y = r / 56, xx = r - y * 56;
        int wv = (y / 7) * 8 + (xx / 7);
        int tk = (y % 7) * 7 + (xx % 7);
        abase = g_atth + b * 602112 + wv * 1568 + tk * 32;
    }
    const int bn = tid >> 2, bq = tid & 3;

    uint32_t a_s[2], b_s[2];
    a_s[0] = smem_u32(As[0]); a_s[1] = smem_u32(As[1]);
    b_s[0] = smem_u32(Bs[0]); b_s[1] = smem_u32(Bs[1]);

    const int lr = lane & 7, lm = (lane >> 3) & 1, lk = lane >> 4;
    const uint32_t aoff = (uint32_t)((wm * 64 + lr + lm * 8) * LDA + lk * 8) * 2;
    const uint32_t boff = (uint32_t)((wn * 48 + lr + lm * 8) * LDA + lk * 8) * 2;

#define LD_CHUNK_P(cc, ss) do { \
        uint32_t ad = a_s[ss] + (uint32_t)(tid * LDA) * 2; \
        const __half* asrc = abase + (cc) * 100352; \
        cpa16(ad + 0,  asrc + 0);  cpa16(ad + 16, asrc + 8); \
        cpa16(ad + 32, asrc + 16); cpa16(ad + 48, asrc + 24); \
        _Pragma("unroll") \
        for (int ii = 0; ii < 3; ii++) { \
            int n = bn + ii * 32; \
            cpa16(b_s[ss] + (uint32_t)(n * LDA + bq * 8) * 2, \
                  g_woh + (size_t)(nb * 96 + n) * 192 + (cc) * 32 + bq * 8); \
        } \
        CP_COMMIT(); } while (0)

    float c[4][6][4] = {};
    LD_CHUNK_P(0, 0);

#pragma unroll 1
    for (int ch = 0; ch < 6; ch++) {
        const int s = ch & 1;
        if (ch < 5) { LD_CHUNK_P(ch + 1, s ^ 1); CP_WAIT1(); }
        else        { CP_WAIT0(); }
        __syncthreads();

#pragma unroll
        for (int kk = 0; kk < 32; kk += 16) {
            uint32_t af[4][4], bf[6][2];
#pragma unroll
            for (int mi = 0; mi < 4; mi++)
                ldsm4(af[mi], a_s[s] + aoff + (uint32_t)(mi * 16 * LDA + kk) * 2);
#pragma unroll
            for (int nj = 0; nj < 3; nj++) {
                uint32_t r[4];
                ldsm4(r, b_s[s] + boff + (uint32_t)(nj * 16 * LDA + kk) * 2);
                bf[2 * nj][0] = r[0]; bf[2 * nj + 1][0] = r[1];
                bf[2 * nj][1] = r[2]; bf[2 * nj + 1][1] = r[3];
            }
#pragma unroll
            for (int mi = 0; mi < 4; mi++)
#pragma unroll
                for (int ni = 0; ni < 6; ni++)
                    mma16(c[mi][ni], af[mi], bf[ni]);
        }
        __syncthreads();
    }

#pragma unroll
    for (int mi = 0; mi < 4; mi++) {
#pragma unroll
        for (int half = 0; half < 2; half++) {
            int r = bm + wm * 64 + mi * 16 + g + half * 8;
            int b = r / 3136; int rr = r - b * 3136;
            int y = rr / 56, xx = rr - y * 56;
            int yo = y + 3;  if (yo >= 56) yo -= 56;
            int xo = xx + 3; if (xo >= 56) xo -= 56;
            float* op = out + ((b * 56 + yo) * 56 + xo) * 192;
#pragma unroll
            for (int ni = 0; ni < 6; ni++) {
                int cp = nb * 96 + wn * 48 + ni * 8 + tg * 2;
                float2 bb = *(const float2*)(bout + cp);
                float2 v = make_float2(c[mi][ni][half * 2] + bb.x,
                                       c[mi][ni][half * 2 + 1] + bb.y);
                *(float2*)(op + cp) = v;
            }
        }
    }
}

// ================= launch =================
extern "C" void kernel_launch(void* const* d_in, const int* in_sizes, int n_in,
                              void* d_out, int out_size)
{
    const float* x    = (const float*)d_in[0];
    const float* wqkv = (const float*)d_in[1];
    const float* pe   = (const float*)d_in[2];
    const float* wout = (const float*)d_in[3];
    const float* bout = (const float*)d_in[4];
    float* out = (float*)d_out;

    prep_x<<<9408, 256>>>(x);
    prep_w<<<108, 256>>>(wqkv);
    prep_wo<<<36, 256>>>(wout);

    dim3 g1(392, 6);
    qkv_gemm<<<g1, 128>>>();

    attn_hmma<<<16 * 6 * 64, 128>>>(pe);

    dim3 g3(392, 2);
    proj_gemm<<<g3, 128>>>(bout, out);
}

// round 8
// speedup vs baseline: 1.0482x; 1.0482x over previous
#include <cuda_runtime.h>
#include <cuda_fp16.h>
#include <cstdint>

#define QT (16*6*64*49*32)            // 9,633,792 elements per q/k/v tensor

__device__ __half g_xh[50176 * 192];  // rolled x, fp16, token-major
__device__ __half g_wh[576 * 192];    // wqkv^T [n][k] fp16
__device__ __half g_woh[192 * 192];   // wout^T [n][k] fp16
__device__ __half g_qkvh[3u * QT];    // q|k|v fp16, window layout [b,h,win,49,32]
__device__ __half g_atth[QT];         // attention out fp16, window layout

// ---------------- helpers ----------------
__device__ __forceinline__ void mma16(float* c, const uint32_t* a, const uint32_t* b) {
    asm volatile("mma.sync.aligned.m16n8k16.row.col.f32.f16.f16.f32 "
        "{%0,%1,%2,%3}, {%4,%5,%6,%7}, {%8,%9}, {%0,%1,%2,%3};\n"
        : "+f"(c[0]), "+f"(c[1]), "+f"(c[2]), "+f"(c[3])
        : "r"(a[0]), "r"(a[1]), "r"(a[2]), "r"(a[3]), "r"(b[0]), "r"(b[1]));
}
__device__ __forceinline__ void cpa16(uint32_t s, const void* g) {
    asm volatile("cp.async.cg.shared.global [%0], [%1], 16;" :: "r"(s), "l"(g));
}
#define CP_COMMIT() asm volatile("cp.async.commit_group;")
#define CP_WAIT2()  asm volatile("cp.async.wait_group 2;")
#define CP_WAIT1()  asm volatile("cp.async.wait_group 1;")
#define CP_WAIT0()  asm volatile("cp.async.wait_group 0;")
__device__ __forceinline__ uint32_t smem_u32(const void* p) {
    uint32_t a;
    asm("{ .reg .u64 t; cvta.to.shared.u64 t, %1; cvt.u32.u64 %0, t; }" : "=r"(a) : "l"(p));
    return a;
}
__device__ __forceinline__ uint32_t h2u(__half2 h) { return *reinterpret_cast<uint32_t*>(&h); }

// ================= prep kernels =================
__global__ __launch_bounds__(256) void prep_x(const float* __restrict__ x) {
    int i = blockIdx.x * 256 + threadIdx.x;
    int e = i * 4;
    int t = e / 192, c = e - t * 192;
    int b = t / 3136; int r = t - b * 3136;
    int y = r / 56, xx = r - y * 56;
    int ys = y + 3;  if (ys >= 56) ys -= 56;
    int xs = xx + 3; if (xs >= 56) xs -= 56;
    float4 v = *(const float4*)(x + ((b * 56 + ys) * 56 + xs) * 192 + c);
    *(__half2*)(g_xh + e)     = __floats2half2_rn(v.x, v.y);
    *(__half2*)(g_xh + e + 2) = __floats2half2_rn(v.z, v.w);
}
__global__ __launch_bounds__(256) void prep_w(const float* __restrict__ w) {
    int i = blockIdx.x * 256 + threadIdx.x;
    int e = i * 4;
    int n = e / 192, k = e - n * 192;
#pragma unroll
    for (int j = 0; j < 4; j++)
        g_wh[e + j] = __float2half_rn(w[(k + j) * 576 + n]);
}
__global__ __launch_bounds__(256) void prep_wo(const float* __restrict__ w) {
    int i = blockIdx.x * 256 + threadIdx.x;
    int e = i * 4;
    int n = e / 192, k = e - n * 192;
#pragma unroll
    for (int j = 0; j < 4; j++)
        g_woh[e + j] = __float2half_rn(w[(k + j) * 192 + n]);
}

// ============ fp16 GEMM: BM=128, BN=96, BK=32, 128 threads, 3-stage cp.async ============
#define LDA 40
#define A_ST (128 * LDA)            // 5120 halves
#define B_ST (96 * LDA)             // 3840 halves
#define STAGE (A_ST + B_ST)         // 8960 halves = 17920 B
#define GSMEM (3 * STAGE * 2)       // 53760 B dynamic

// ================= Kernel 1: QKV GEMM =================
__global__ __launch_bounds__(128, 3) void qkv_gemm(void)
{
    extern __shared__ __align__(16) __half sm[];

    const int tid  = threadIdx.x;
    const int warp = tid >> 5, lane = tid & 31;
    const int wm   = warp & 1, wn = warp >> 1;
    const int g    = lane >> 2, tg = lane & 3;
    const int bm   = blockIdx.x * 128;
    const int nb   = blockIdx.y;

    const __half* ap = g_xh + (size_t)(bm + tid) * 192;
    const int bn = tid >> 2, bq = tid & 3;
    const uint32_t smb = smem_u32(sm);

#define LD_CHUNK(cc, ss) do { \
        uint32_t ad = smb + (uint32_t)((ss) * STAGE + tid * LDA) * 2; \
        const __half* asrc = ap + (cc) * 32; \
        cpa16(ad + 0,  asrc + 0);  cpa16(ad + 16, asrc + 8); \
        cpa16(ad + 32, asrc + 16); cpa16(ad + 48, asrc + 24); \
        uint32_t bd = smb + (uint32_t)((ss) * STAGE + A_ST) * 2; \
        _Pragma("unroll") \
        for (int ii = 0; ii < 3; ii++) { \
            int n = bn + ii * 32; \
            cpa16(bd + (uint32_t)(n * LDA + bq * 8) * 2, \
                  g_wh + (size_t)(nb * 96 + n) * 192 + (cc) * 32 + bq * 8); \
        } \
        CP_COMMIT(); } while (0)

    float c[4][6][4] = {};
    LD_CHUNK(0, 0);
    LD_CHUNK(1, 1);

    int st = 0;
#pragma unroll 1
    for (int ch = 0; ch < 6; ch++) {
        __syncthreads();                       // stage (st+2)%3 free to overwrite
        if (ch < 4) {
            int s2 = st + 2; if (s2 >= 3) s2 -= 3;
            LD_CHUNK(ch + 2, s2);
        }
        if (ch < 4)       CP_WAIT2();
        else if (ch == 4) CP_WAIT1();
        else              CP_WAIT0();
        __syncthreads();

        const __half* Ab = sm + st * STAGE;
        const __half* Bb = Ab + A_ST;
#pragma unroll
        for (int kk = 0; kk < 32; kk += 16) {
            uint32_t af[4][4], bf[6][2];
#pragma unroll
            for (int mi = 0; mi < 4; mi++) {
                const __half* pa = Ab + (wm * 64 + mi * 16 + g) * LDA + kk + 2 * tg;
                af[mi][0] = *(const uint32_t*)(pa);
                af[mi][1] = *(const uint32_t*)(pa + 8 * LDA);
                af[mi][2] = *(const uint32_t*)(pa + 8);
                af[mi][3] = *(const uint32_t*)(pa + 8 * LDA + 8);
            }
#pragma unroll
            for (int ni = 0; ni < 6; ni++) {
                const __half* pb = Bb + (wn * 48 + ni * 8 + g) * LDA + kk + 2 * tg;
                bf[ni][0] = *(const uint32_t*)(pb);
                bf[ni][1] = *(const uint32_t*)(pb + 8);
            }
#pragma unroll
            for (int mi = 0; mi < 4; mi++)
#pragma unroll
                for (int ni = 0; ni < 6; ni++)
                    mma16(c[mi][ni], af[mi], bf[ni]);
        }
        st++; if (st == 3) st = 0;
    }

    const int t = nb >> 1;
    __half* qb = g_qkvh + (size_t)t * QT;
#pragma unroll
    for (int mi = 0; mi < 4; mi++) {
#pragma unroll
        for (int half = 0; half < 2; half++) {
            int r = bm + wm * 64 + mi * 16 + g + half * 8;
            int b = r / 3136; int rr = r - b * 3136;
            int y = rr / 56, xx = rr - y * 56;
            int wv = (y / 7) * 8 + (xx / 7);
            int tk = (y % 7) * 7 + (xx % 7);
            __half* base = qb + b * 602112 + wv * 1568 + tk * 32;
#pragma unroll
            for (int ni = 0; ni < 6; ni++) {
                int cp = nb * 96 + wn * 48 + ni * 8 + tg * 2;
                int cc = cp - t * 192;
                int h = cc >> 5, d = cc & 31;
                *(__half2*)(base + h * 100352 + d) =
                    __floats2half2_rn(c[mi][ni][half * 2], c[mi][ni][half * 2 + 1]);
            }
        }
    }
}

// ================= Kernel 2: HMMA attention (R6 exact) =================
#define LDQ 40
#define LDV 72

__global__ __launch_bounds__(128) void attn_hmma(const float* __restrict__ pe)
{
    __shared__ __align__(16) __half Qs[64 * LDQ];
    __shared__ __align__(16) __half Ks[64 * LDQ];
    __shared__ __align__(16) __half Vt[32 * LDV];
    __shared__ float PE[169];

    const int tid = threadIdx.x;
    const int w = tid >> 5, lane = tid & 31;
    const int g = lane >> 2, t = lane & 3;
    const int bx = blockIdx.x;
    const int wv = bx & 63;
    const int wy = wv >> 3, wx = wv & 7;
    const bool mrow = (wy == 7), mcol = (wx == 7);

    const __half2* qg = (const __half2*)(g_qkvh + (size_t)bx * 1568);
    const __half2* kg = (const __half2*)(g_qkvh + (size_t)QT + (size_t)bx * 1568);
    const __half2* vg = (const __half2*)(g_qkvh + 2 * (size_t)QT + (size_t)bx * 1568);

    const __half2 z2 = __floats2half2_rn(0.f, 0.f);
    for (int p = tid; p < 1280; p += 128) {
        int i = p / 20, dp = p - i * 20;
        __half2 qv = z2, kv = z2;
        if (dp < 16 && i < 49) { qv = qg[i * 16 + dp]; kv = kg[i * 16 + dp]; }
        *(__half2*)(Qs + i * LDQ + dp * 2) = qv;
        *(__half2*)(Ks + i * LDQ + dp * 2) = kv;
    }
    for (int p = tid; p < 784; p += 128) {
        int i = p >> 4, dp = p & 15;
        __half2 v = vg[p];
        Vt[(2 * dp) * LDV + i]     = __low2half(v);
        Vt[(2 * dp + 1) * LDV + i] = __high2half(v);
    }
    for (int p = tid; p < 480; p += 128) {
        int d = p / 15, c = 49 + (p - d * 15);
        Vt[d * LDV + c] = __float2half_rn(0.f);
    }
    for (int p = tid; p < 169; p += 128) PE[p] = pe[p];
    __syncthreads();

    float S[8][4] = {};
    const __half* qrow = Qs + (w * 16 + g) * LDQ;
#pragma unroll
    for (int kk = 0; kk < 32; kk += 16) {
        uint32_t a[4];
        a[0] = *(const uint32_t*)(qrow + kk + 2 * t);
        a[1] = *(const uint32_t*)(qrow + 8 * LDQ + kk + 2 * t);
        a[2] = *(const uint32_t*)(qrow + kk + 8 + 2 * t);
        a[3] = *(const uint32_t*)(qrow + 8 * LDQ + kk + 8 + 2 * t);
#pragma unroll
        for (int n = 0; n < 8; n++) {
            uint32_t b[2];
            const __half* kb = Ks + (n * 8 + g) * LDQ + kk + 2 * t;
            b[0] = *(const uint32_t*)(kb);
            b[1] = *(const uint32_t*)(kb + 8);
            mma16(S[n], a, b);
        }
    }

    const float scale = 0.17677669529663687f;
#pragma unroll
    for (int rw = 0; rw < 2; rw++) {
        int i = w * 16 + g + rw * 8;
        int ic = (i < 49) ? i : 48;
        int iy = ic / 7, ix = ic - iy * 7;
        float mx = -1e30f;
#pragma unroll
        for (int n = 0; n < 8; n++) {
#pragma unroll
            for (int e = 0; e < 2; e++) {
                int j = n * 8 + 2 * t + e;
                float v;
                if (j < 49) {
                    int jy = j / 7, jx = j - jy * 7;
                    v = S[n][rw * 2 + e] * scale + PE[(jy - iy + 6) * 13 + (jx - ix + 6)];
                    if (mrow && ((iy >= 4) != (jy >= 4))) v -= 1e9f;
                    if (mcol && ((ix >= 4) != (jx >= 4))) v -= 1e9f;
                } else {
                    v = -1e9f;
                }
                S[n][rw * 2 + e] = v;
                mx = fmaxf(mx, v);
            }
        }
        mx = fmaxf(mx, __shfl_xor_sync(0xffffffffu, mx, 1));
        mx = fmaxf(mx, __shfl_xor_sync(0xffffffffu, mx, 2));
        float sm = 0.f;
#pragma unroll
        for (int n = 0; n < 8; n++) {
#pragma unroll
            for (int e = 0; e < 2; e++) {
                float ex = __expf(S[n][rw * 2 + e] - mx);
                S[n][rw * 2 + e] = ex;
                sm += ex;
            }
        }
        sm += __shfl_xor_sync(0xffffffffu, sm, 1);
        sm += __shfl_xor_sync(0xffffffffu, sm, 2);
        float inv = 1.f / sm;
#pragma unroll
        for (int n = 0; n < 8; n++) {
            S[n][rw * 2 + 0] *= inv;
            S[n][rw * 2 + 1] *= inv;
        }
    }

    uint32_t Pa[4][4];
#pragma unroll
    for (int c = 0; c < 4; c++) {
        Pa[c][0] = h2u(__floats2half2_rn(S[2 * c][0],     S[2 * c][1]));
        Pa[c][1] = h2u(__floats2half2_rn(S[2 * c][2],     S[2 * c][3]));
        Pa[c][2] = h2u(__floats2half2_rn(S[2 * c + 1][0], S[2 * c + 1][1]));
        Pa[c][3] = h2u(__floats2half2_rn(S[2 * c + 1][2], S[2 * c + 1][3]));
    }

    float O[4][4] = {};
#pragma unroll
    for (int c = 0; c < 4; c++) {
#pragma unroll
        for (int nt = 0; nt < 4; nt++) {
            uint32_t b[2];
            const __half* vb = Vt + (nt * 8 + g) * LDV + c * 16 + 2 * t;
            b[0] = *(const uint32_t*)(vb);
            b[1] = *(const uint32_t*)(vb + 8);
            mma16(O[nt], Pa[c], b);
        }
    }

    __half* og = g_atth + (size_t)bx * 1568;
#pragma unroll
    for (int rw = 0; rw < 2; rw++) {
        int i = w * 16 + g + rw * 8;
        if (i < 49) {
#pragma unroll
            for (int nt = 0; nt < 4; nt++)
                *(__half2*)(og + i * 32 + nt * 8 + 2 * t) =
                    __floats2half2_rn(O[nt][rw * 2], O[nt][rw * 2 + 1]);
        }
    }
}

// ================= Kernel 3: out-proj GEMM + inverse roll (3-stage) =================
__global__ __launch_bounds__(128, 3) void proj_gemm(
    const float* __restrict__ bout, float* __restrict__ out)
{
    extern __shared__ __align__(16) __half sm[];

    const int tid  = threadIdx.x;
    const int warp = tid >> 5, lane = tid & 31;
    const int wm   = warp & 1, wn = warp >> 1;
    const int g    = lane >> 2, tg = lane & 3;
    const int bm   = blockIdx.x * 128;
    const int nb   = blockIdx.y;

    const __half* abase;
    {
        int row = bm + tid;
        int b = row / 3136; int r = row - b * 3136;
        int y = r / 56, xx = r - y * 56;
        int wv = (y / 7) * 8 + (xx / 7);
        int tk = (y % 7) * 7 + (xx % 7);
        abase = g_atth + b * 602112 + wv * 1568 + tk * 32;   // chunk c = head c
    }
    const int bn = tid >> 2, bq = tid & 3;
    const uint32_t smb = smem_u32(sm);

#define LD_CHUNK_P(cc, ss) do { \
        uint32_t ad = smb + (uint32_t)((ss) * STAGE + tid * LDA) * 2; \
        const __half* asrc = abase + (cc) * 100352; \
        cpa16(ad + 0,  asrc + 0);  cpa16(ad + 16, asrc + 8); \
        cpa16(ad + 32, asrc + 16); cpa16(ad + 48, asrc + 24); \
        uint32_t bd = smb + (uint32_t)((ss) * STAGE + A_ST) * 2; \
        _Pragma("unroll") \
        for (int ii = 0; ii < 3; ii++) { \
            int n = bn + ii * 32; \
            cpa16(bd + (uint32_t)(n * LDA + bq * 8) * 2, \
                  g_woh + (size_t)(nb * 96 + n) * 192 + (cc) * 32 + bq * 8); \
        } \
        CP_COMMIT(); } while (0)

    float c[4][6][4] = {};
    LD_CHUNK_P(0, 0);
    LD_CHUNK_P(1, 1);

    int st = 0;
#pragma unroll 1
    for (int ch = 0; ch < 6; ch++) {
        __syncthreads();
        if (ch < 4) {
            int s2 = st + 2; if (s2 >= 3) s2 -= 3;
            LD_CHUNK_P(ch + 2, s2);
        }
        if (ch < 4)       CP_WAIT2();
        else if (ch == 4) CP_WAIT1();
        else              CP_WAIT0();
        __syncthreads();

        const __half* Ab = sm + st * STAGE;
        const __half* Bb = Ab + A_ST;
#pragma unroll
        for (int kk = 0; kk < 32; kk += 16) {
            uint32_t af[4][4], bf[6][2];
#pragma unroll
            for (int mi = 0; mi < 4; mi++) {
                const __half* pa = Ab + (wm * 64 + mi * 16 + g) * LDA + kk + 2 * tg;
                af[mi][0] = *(const uint32_t*)(pa);
                af[mi][1] = *(const uint32_t*)(pa + 8 * LDA);
                af[mi][2] = *(const uint32_t*)(pa + 8);
                af[mi][3] = *(const uint32_t*)(pa + 8 * LDA + 8);
            }
#pragma unroll
            for (int ni = 0; ni < 6; ni++) {
                const __half* pb = Bb + (wn * 48 + ni * 8 + g) * LDA + kk + 2 * tg;
                bf[ni][0] = *(const uint32_t*)(pb);
                bf[ni][1] = *(const uint32_t*)(pb + 8);
            }
#pragma unroll
            for (int mi = 0; mi < 4; mi++)
#pragma unroll
                for (int ni = 0; ni < 6; ni++)
                    mma16(c[mi][ni], af[mi], bf[ni]);
        }
        st++; if (st == 3) st = 0;
    }

#pragma unroll
    for (int mi = 0; mi < 4; mi++) {
#pragma unroll
        for (int half = 0; half < 2; half++) {
            int r = bm + wm * 64 + mi * 16 + g + half * 8;
            int b = r / 3136; int rr = r - b * 3136;
            int y = rr / 56, xx = rr - y * 56;
            int yo = y + 3;  if (yo >= 56) yo -= 56;
            int xo = xx + 3; if (xo >= 56) xo -= 56;
            float* op = out + ((b * 56 + yo) * 56 + xo) * 192;
#pragma unroll
            for (int ni = 0; ni < 6; ni++) {
                int cp = nb * 96 + wn * 48 + ni * 8 + tg * 2;
                float2 bb = *(const float2*)(bout + cp);
                float2 v = make_float2(c[mi][ni][half * 2] + bb.x,
                                       c[mi][ni][half * 2 + 1] + bb.y);
                *(float2*)(op + cp) = v;
            }
        }
    }
}

// ================= launch =================
extern "C" void kernel_launch(void* const* d_in, const int* in_sizes, int n_in,
                              void* d_out, int out_size)
{
    const float* x    = (const float*)d_in[0];
    const float* wqkv = (const float*)d_in[1];
    const float* pe   = (const float*)d_in[2];
    const float* wout = (const float*)d_in[3];
    const float* bout = (const float*)d_in[4];
    float* out = (float*)d_out;

    static int configured = 0;
    if (!configured) {
        cudaFuncSetAttribute(qkv_gemm, cudaFuncAttributeMaxDynamicSharedMemorySize, GSMEM);
        cudaFuncSetAttribute(proj_gemm, cudaFuncAttributeMaxDynamicSharedMemorySize, GSMEM);
        configured = 1;
    }

    prep_x<<<9408, 256>>>(x);
    prep_w<<<108, 256>>>(wqkv);
    prep_wo<<<36, 256>>>(wout);

    dim3 g1(392, 6);
    qkv_gemm<<<g1, 128, GSMEM>>>();

    attn_hmma<<<16 * 6 * 64, 128>>>(pe);

    dim3 g3(392, 2);
    proj_gemm<<<g3, 128, GSMEM>>>(bout, out);
}

// round 9
// speedup vs baseline: 1.0887x; 1.0386x over previous
#include <cuda_runtime.h>
#include <cuda_fp16.h>
#include <cstdint>

#define QT (16*6*64*49*32)            // 9,633,792 elements per q/k/v tensor

// K-dimension tensors use pair-interleaved layout within each 16-half k-group:
// orig pair q (halves 2q,2q+1) stored at pair ((q&3)<<1)|(q>>2).
__device__ __half g_xh[50176 * 192];  // rolled x, fp16, permuted-k
__device__ __half g_wh[576 * 192];    // wqkv^T [n][k] fp16, permuted-k
__device__ __half g_woh[192 * 192];   // wout^T [n][k] fp16, permuted-k
__device__ __half g_qkvh[3u * QT];    // q|k|v fp16, window layout (natural)
__device__ __half g_atth[QT];         // attention out fp16, window layout, permuted-k

// ---------------- helpers ----------------
__device__ __forceinline__ void mma16(float* c, const uint32_t* a, const uint32_t* b) {
    asm volatile("mma.sync.aligned.m16n8k16.row.col.f32.f16.f16.f32 "
        "{%0,%1,%2,%3}, {%4,%5,%6,%7}, {%8,%9}, {%0,%1,%2,%3};\n"
        : "+f"(c[0]), "+f"(c[1]), "+f"(c[2]), "+f"(c[3])
        : "r"(a[0]), "r"(a[1]), "r"(a[2]), "r"(a[3]), "r"(b[0]), "r"(b[1]));
}
__device__ __forceinline__ void cpa16(uint32_t s, const void* g) {
    asm volatile("cp.async.cg.shared.global [%0], [%1], 16;" :: "r"(s), "l"(g));
}
#define CP_COMMIT() asm volatile("cp.async.commit_group;")
#define CP_WAIT2()  asm volatile("cp.async.wait_group 2;")
#define CP_WAIT1()  asm volatile("cp.async.wait_group 1;")
#define CP_WAIT0()  asm volatile("cp.async.wait_group 0;")
__device__ __forceinline__ uint32_t smem_u32(const void* p) {
    uint32_t a;
    asm("{ .reg .u64 t; cvta.to.shared.u64 t, %1; cvt.u32.u64 %0, t; }" : "=r"(a) : "l"(p));
    return a;
}
__device__ __forceinline__ uint32_t h2u(__half2 h) { return *reinterpret_cast<uint32_t*>(&h); }

// ================= prep kernels (write permuted-k) =================
__global__ __launch_bounds__(256) void prep_x(const float* __restrict__ x) {
    int i = blockIdx.x * 256 + threadIdx.x;
    int e = i * 4;                               // e % 4 == 0
    int t = e / 192, c = e - t * 192;
    int b = t / 3136; int r = t - b * 3136;
    int y = r / 56, xx = r - y * 56;
    int ys = y + 3;  if (ys >= 56) ys -= 56;
    int xs = xx + 3; if (xs >= 56) xs -= 56;
    float4 v = *(const float4*)(x + ((b * 56 + ys) * 56 + xs) * 192 + c);
    int gb = e & ~15;
    int q = (e >> 1) & 7;                        // even
    int p0 = ((q & 3) << 1) | (q >> 2);
    int q1 = q + 1;
    int p1 = ((q1 & 3) << 1) | (q1 >> 2);
    *(__half2*)(g_xh + gb + 2 * p0) = __floats2half2_rn(v.x, v.y);
    *(__half2*)(g_xh + gb + 2 * p1) = __floats2half2_rn(v.z, v.w);
}
__global__ __launch_bounds__(256) void prep_wb(const float* __restrict__ w,
                                               const float* __restrict__ wo) {
    int i = blockIdx.x * 256 + threadIdx.x;      // 36864 total
    int e = i * 4;
    __half* dst;
    float vv[4];
    if (e < 110592) {                            // wqkv^T
        int n = e / 192, k = e - n * 192;
#pragma unroll
        for (int j = 0; j < 4; j++) vv[j] = w[(k + j) * 576 + n];
        dst = g_wh;
    } else {                                     // wout^T
        int e2 = e - 110592;
        int n = e2 / 192, k = e2 - n * 192;
#pragma unroll
        for (int j = 0; j < 4; j++) vv[j] = wo[(k + j) * 192 + n];
        dst = g_woh - 110592;
    }
    int gb = e & ~15;
    int q = (e >> 1) & 7;
    int p0 = ((q & 3) << 1) | (q >> 2);
    int q1 = q + 1;
    int p1 = ((q1 & 3) << 1) | (q1 >> 2);
    *(__half2*)(dst + gb + 2 * p0) = __floats2half2_rn(vv[0], vv[1]);
    *(__half2*)(dst + gb + 2 * p1) = __floats2half2_rn(vv[2], vv[3]);
}

// ============ fp16 GEMM: BM=128, BN=96, BK=32, 128 threads, 3-stage, LDA=48 ============
#define LDA 48
#define A_ST (128 * LDA)
#define B_ST (96 * LDA)
#define STAGE (A_ST + B_ST)
#define GSMEM (3 * STAGE * 2)        // 64512 B dynamic

// ================= Kernel 1: QKV GEMM =================
__global__ __launch_bounds__(128, 3) void qkv_gemm(void)
{
    extern __shared__ __align__(16) __half sm[];

    const int tid  = threadIdx.x;
    const int warp = tid >> 5, lane = tid & 31;
    const int wm   = warp & 1, wn = warp >> 1;
    const int g    = lane >> 2, tg = lane & 3;
    const int bm   = blockIdx.x * 128;
    const int nb   = blockIdx.y;

    const __half* ap = g_xh + (size_t)(bm + tid) * 192;
    const int bn = tid >> 2, bq = tid & 3;
    const uint32_t smb = smem_u32(sm);

#define LD_CHUNK(cc, ss) do { \
        uint32_t ad = smb + (uint32_t)((ss) * STAGE + tid * LDA) * 2; \
        const __half* asrc = ap + (cc) * 32; \
        cpa16(ad + 0,  asrc + 0);  cpa16(ad + 16, asrc + 8); \
        cpa16(ad + 32, asrc + 16); cpa16(ad + 48, asrc + 24); \
        uint32_t bd = smb + (uint32_t)((ss) * STAGE + A_ST) * 2; \
        _Pragma("unroll") \
        for (int ii = 0; ii < 3; ii++) { \
            int n = bn + ii * 32; \
            cpa16(bd + (uint32_t)(n * LDA + bq * 8) * 2, \
                  g_wh + (size_t)(nb * 96 + n) * 192 + (cc) * 32 + bq * 8); \
        } \
        CP_COMMIT(); } while (0)

    float c[4][6][4] = {};
    LD_CHUNK(0, 0);
    LD_CHUNK(1, 1);

    int st = 0;
#pragma unroll 1
    for (int ch = 0; ch < 6; ch++) {
        __syncthreads();
        if (ch < 4) {
            int s2 = st + 2; if (s2 >= 3) s2 -= 3;
            LD_CHUNK(ch + 2, s2);
        }
        if (ch < 4)       CP_WAIT2();
        else if (ch == 4) CP_WAIT1();
        else              CP_WAIT0();
        __syncthreads();

        const __half* Ab = sm + st * STAGE;
        const __half* Bb = Ab + A_ST;
#pragma unroll
        for (int kk = 0; kk < 32; kk += 16) {
            uint32_t af[4][4], bf[6][2];
#pragma unroll
            for (int mi = 0; mi < 4; mi++) {
                const int rb = wm * 64 + mi * 16 + g;
                uint2 v0 = *(const uint2*)(Ab + rb * LDA + kk + 4 * tg);
                uint2 v1 = *(const uint2*)(Ab + (rb + 8) * LDA + kk + 4 * tg);
                af[mi][0] = v0.x; af[mi][2] = v0.y;
                af[mi][1] = v1.x; af[mi][3] = v1.y;
            }
#pragma unroll
            for (int ni = 0; ni < 6; ni++) {
                uint2 vb = *(const uint2*)(Bb + (wn * 48 + ni * 8 + g) * LDA + kk + 4 * tg);
                bf[ni][0] = vb.x; bf[ni][1] = vb.y;
            }
#pragma unroll
            for (int mi = 0; mi < 4; mi++)
#pragma unroll
                for (int ni = 0; ni < 6; ni++)
                    mma16(c[mi][ni], af[mi], bf[ni]);
        }
        st++; if (st == 3) st = 0;
    }

    // epilogue: natural-layout scatter into window layout
    const int t = nb >> 1;
    __half* qb = g_qkvh + (size_t)t * QT;
#pragma unroll
    for (int mi = 0; mi < 4; mi++) {
#pragma unroll
        for (int half = 0; half < 2; half++) {
            int r = bm + wm * 64 + mi * 16 + g + half * 8;
            int b = r / 3136; int rr = r - b * 3136;
            int y = rr / 56, xx = rr - y * 56;
            int wv = (y / 7) * 8 + (xx / 7);
            int tk = (y % 7) * 7 + (xx % 7);
            __half* base = qb + b * 602112 + wv * 1568 + tk * 32;
#pragma unroll
            for (int ni = 0; ni < 6; ni++) {
                int cp = nb * 96 + wn * 48 + ni * 8 + tg * 2;
                int cc = cp - t * 192;
                int h = cc >> 5, d = cc & 31;
                *(__half2*)(base + h * 100352 + d) =
                    __floats2half2_rn(c[mi][ni][half * 2], c[mi][ni][half * 2 + 1]);
            }
        }
    }
}

// ================= Kernel 2: HMMA attention (R6 compute; permuted-k store) =================
#define LDQ 40
#define LDV 72

__global__ __launch_bounds__(128) void attn_hmma(const float* __restrict__ pe)
{
    __shared__ __align__(16) __half Qs[64 * LDQ];
    __shared__ __align__(16) __half Ks[64 * LDQ];
    __shared__ __align__(16) __half Vt[32 * LDV];
    __shared__ float PE[169];

    const int tid = threadIdx.x;
    const int w = tid >> 5, lane = tid & 31;
    const int g = lane >> 2, t = lane & 3;
    const int bx = blockIdx.x;
    const int wv = bx & 63;
    const int wy = wv >> 3, wx = wv & 7;
    const bool mrow = (wy == 7), mcol = (wx == 7);

    const __half2* qg = (const __half2*)(g_qkvh + (size_t)bx * 1568);
    const __half2* kg = (const __half2*)(g_qkvh + (size_t)QT + (size_t)bx * 1568);
    const __half2* vg = (const __half2*)(g_qkvh + 2 * (size_t)QT + (size_t)bx * 1568);

    const __half2 z2 = __floats2half2_rn(0.f, 0.f);
    for (int p = tid; p < 1280; p += 128) {
        int i = p / 20, dp = p - i * 20;
        __half2 qv = z2, kv = z2;
        if (dp < 16 && i < 49) { qv = qg[i * 16 + dp]; kv = kg[i * 16 + dp]; }
        *(__half2*)(Qs + i * LDQ + dp * 2) = qv;
        *(__half2*)(Ks + i * LDQ + dp * 2) = kv;
    }
    for (int p = tid; p < 784; p += 128) {
        int i = p >> 4, dp = p & 15;
        __half2 v = vg[p];
        Vt[(2 * dp) * LDV + i]     = __low2half(v);
        Vt[(2 * dp + 1) * LDV + i] = __high2half(v);
    }
    for (int p = tid; p < 480; p += 128) {
        int d = p / 15, c = 49 + (p - d * 15);
        Vt[d * LDV + c] = __float2half_rn(0.f);
    }
    for (int p = tid; p < 169; p += 128) PE[p] = pe[p];
    __syncthreads();

    float S[8][4] = {};
    const __half* qrow = Qs + (w * 16 + g) * LDQ;
#pragma unroll
    for (int kk = 0; kk < 32; kk += 16) {
        uint32_t a[4];
        a[0] = *(const uint32_t*)(qrow + kk + 2 * t);
        a[1] = *(const uint32_t*)(qrow + 8 * LDQ + kk + 2 * t);
        a[2] = *(const uint32_t*)(qrow + kk + 8 + 2 * t);
        a[3] = *(const uint32_t*)(qrow + 8 * LDQ + kk + 8 + 2 * t);
#pragma unroll
        for (int n = 0; n < 8; n++) {
            uint32_t b[2];
            const __half* kb = Ks + (n * 8 + g) * LDQ + kk + 2 * t;
            b[0] = *(const uint32_t*)(kb);
            b[1] = *(const uint32_t*)(kb + 8);
            mma16(S[n], a, b);
        }
    }

    const float scale = 0.17677669529663687f;
#pragma unroll
    for (int rw = 0; rw < 2; rw++) {
        int i = w * 16 + g + rw * 8;
        int ic = (i < 49) ? i : 48;
        int iy = ic / 7, ix = ic - iy * 7;
        float mx = -1e30f;
#pragma unroll
        for (int n = 0; n < 8; n++) {
#pragma unroll
            for (int e = 0; e < 2; e++) {
                int j = n * 8 + 2 * t + e;
                float v;
                if (j < 49) {
                    int jy = j / 7, jx = j - jy * 7;
                    v = S[n][rw * 2 + e] * scale + PE[(jy - iy + 6) * 13 + (jx - ix + 6)];
                    if (mrow && ((iy >= 4) != (jy >= 4))) v -= 1e9f;
                    if (mcol && ((ix >= 4) != (jx >= 4))) v -= 1e9f;
                } else {
                    v = -1e9f;
                }
                S[n][rw * 2 + e] = v;
                mx = fmaxf(mx, v);
            }
        }
        mx = fmaxf(mx, __shfl_xor_sync(0xffffffffu, mx, 1));
        mx = fmaxf(mx, __shfl_xor_sync(0xffffffffu, mx, 2));
        float sm = 0.f;
#pragma unroll
        for (int n = 0; n < 8; n++) {
#pragma unroll
            for (int e = 0; e < 2; e++) {
                float ex = __expf(S[n][rw * 2 + e] - mx);
                S[n][rw * 2 + e] = ex;
                sm += ex;
            }
        }
        sm += __shfl_xor_sync(0xffffffffu, sm, 1);
        sm += __shfl_xor_sync(0xffffffffu, sm, 2);
        float inv = 1.f / sm;
#pragma unroll
        for (int n = 0; n < 8; n++) {
            S[n][rw * 2 + 0] *= inv;
            S[n][rw * 2 + 1] *= inv;
        }
    }

    uint32_t Pa[4][4];
#pragma unroll
    for (int c = 0; c < 4; c++) {
        Pa[c][0] = h2u(__floats2half2_rn(S[2 * c][0],     S[2 * c][1]));
        Pa[c][1] = h2u(__floats2half2_rn(S[2 * c][2],     S[2 * c][3]));
        Pa[c][2] = h2u(__floats2half2_rn(S[2 * c + 1][0], S[2 * c + 1][1]));
        Pa[c][3] = h2u(__floats2half2_rn(S[2 * c + 1][2], S[2 * c + 1][3]));
    }

    float O[4][4] = {};
#pragma unroll
    for (int c = 0; c < 4; c++) {
#pragma unroll
        for (int nt = 0; nt < 4; nt++) {
            uint32_t b[2];
            const __half* vb = Vt + (nt * 8 + g) * LDV + c * 16 + 2 * t;
            b[0] = *(const uint32_t*)(vb);
            b[1] = *(const uint32_t*)(vb + 8);
            mma16(O[nt], Pa[c], b);
        }
    }

    // store fp16, permuted-k layout (matches proj_gemm's fragment expectations)
    __half* og = g_atth + (size_t)bx * 1568;
#pragma unroll
    for (int rw = 0; rw < 2; rw++) {
        int i = w * 16 + g + rw * 8;
        if (i < 49) {
#pragma unroll
            for (int nt = 0; nt < 4; nt++) {
                int h = nt * 8 + 2 * t;             // natural half index in [0,32)
                int b16 = h & 16;
                int q = (h >> 1) & 7;
                int pp = ((q & 3) << 1) | (q >> 2);
                *(__half2*)(og + i * 32 + b16 + 2 * pp) =
                    __floats2half2_rn(O[nt][rw * 2], O[nt][rw * 2 + 1]);
            }
        }
    }
}

// ================= Kernel 3: out-proj GEMM + inverse roll (3-stage, LDA=48) =================
__global__ __launch_bounds__(128, 3) void proj_gemm(
    const float* __restrict__ bout, float* __restrict__ out)
{
    extern __shared__ __align__(16) __half sm[];

    const int tid  = threadIdx.x;
    const int warp = tid >> 5, lane = tid & 31;
    const int wm   = warp & 1, wn = warp >> 1;
    const int g    = lane >> 2, tg = lane & 3;
    const int bm   = blockIdx.x * 128;
    const int nb   = blockIdx.y;

    const __half* abase;
    {
        int row = bm + tid;
        int b = row / 3136; int r = row - b * 3136;
        int y = r / 56, xx = r - y * 56;
        int wv = (y / 7) * 8 + (xx / 7);
        int tk = (y % 7) * 7 + (xx % 7);
        abase = g_atth + b * 602112 + wv * 1568 + tk * 32;
    }
    const int bn = tid >> 2, bq = tid & 3;
    const uint32_t smb = smem_u32(sm);

#define LD_CHUNK_P(cc, ss) do { \
        uint32_t ad = smb + (uint32_t)((ss) * STAGE + tid * LDA) * 2; \
        const __half* asrc = abase + (cc) * 100352; \
        cpa16(ad + 0,  asrc + 0);  cpa16(ad + 16, asrc + 8); \
        cpa16(ad + 32, asrc + 16); cpa16(ad + 48, asrc + 24); \
        uint32_t bd = smb + (uint32_t)((ss) * STAGE + A_ST) * 2; \
        _Pragma("unroll") \
        for (int ii = 0; ii < 3; ii++) { \
            int n = bn + ii * 32; \
            cpa16(bd + (uint32_t)(n * LDA + bq * 8) * 2, \
                  g_woh + (size_t)(nb * 96 + n) * 192 + (cc) * 32 + bq * 8); \
        } \
        CP_COMMIT(); } while (0)

    float c[4][6][4] = {};
    LD_CHUNK_P(0, 0);
    LD_CHUNK_P(1, 1);

    int st = 0;
#pragma unroll 1
    for (int ch = 0; ch < 6; ch++) {
        __syncthreads();
        if (ch < 4) {
            int s2 = st + 2; if (s2 >= 3) s2 -= 3;
            LD_CHUNK_P(ch + 2, s2);
        }
        if (ch < 4)       CP_WAIT2();
        else if (ch == 4) CP_WAIT1();
        else              CP_WAIT0();
        __syncthreads();

        const __half* Ab = sm + st * STAGE;
        const __half* Bb = Ab + A_ST;
#pragma unroll
        for (int kk = 0; kk < 32; kk += 16) {
            uint32_t af[4][4], bf[6][2];
#pragma unroll
            for (int mi = 0; mi < 4; mi++) {
                const int rb = wm * 64 + mi * 16 + g;
                uint2 v0 = *(const uint2*)(Ab + rb * LDA + kk + 4 * tg);
                uint2 v1 = *(const uint2*)(Ab + (rb + 8) * LDA + kk + 4 * tg);
                af[mi][0] = v0.x; af[mi][2] = v0.y;
                af[mi][1] = v1.x; af[mi][3] = v1.y;
            }
#pragma unroll
            for (int ni = 0; ni < 6; ni++) {
                uint2 vb = *(const uint2*)(Bb + (wn * 48 + ni * 8 + g) * LDA + kk + 4 * tg);
                bf[ni][0] = vb.x; bf[ni][1] = vb.y;
            }
#pragma unroll
            for (int mi = 0; mi < 4; mi++)
#pragma unroll
                for (int ni = 0; ni < 6; ni++)
                    mma16(c[mi][ni], af[mi], bf[ni]);
        }
        st++; if (st == 3) st = 0;
    }

#pragma unroll
    for (int mi = 0; mi < 4; mi++) {
#pragma unroll
        for (int half = 0; half < 2; half++) {
            int r = bm + wm * 64 + mi * 16 + g + half * 8;
            int b = r / 3136; int rr = r - b * 3136;
            int y = rr / 56, xx = rr - y * 56;
            int yo = y + 3;  if (yo >= 56) yo -= 56;
            int xo = xx + 3; if (xo >= 56) xo -= 56;
            float* op = out + ((b * 56 + yo) * 56 + xo) * 192;
#pragma unroll
            for (int ni = 0; ni < 6; ni++) {
                int cp = nb * 96 + wn * 48 + ni * 8 + tg * 2;
                float2 bb = *(const float2*)(bout + cp);
                float2 v = make_float2(c[mi][ni][half * 2] + bb.x,
                                       c[mi][ni][half * 2 + 1] + bb.y);
                *(float2*)(op + cp) = v;
            }
        }
    }
}

// ================= launch =================
extern "C" void kernel_launch(void* const* d_in, const int* in_sizes, int n_in,
                              void* d_out, int out_size)
{
    const float* x    = (const float*)d_in[0];
    const float* wqkv = (const float*)d_in[1];
    const float* pe   = (const float*)d_in[2];
    const float* wout = (const float*)d_in[3];
    const float* bout = (const float*)d_in[4];
    float* out = (float*)d_out;

    static int configured = 0;
    if (!configured) {
        cudaFuncSetAttribute(qkv_gemm, cudaFuncAttributeMaxDynamicSharedMemorySize, GSMEM);
        cudaFuncSetAttribute(proj_gemm, cudaFuncAttributeMaxDynamicSharedMemorySize, GSMEM);
        configured = 1;
    }

    prep_x<<<9408, 256>>>(x);
    prep_wb<<<144, 256>>>(wqkv, wout);

    dim3 g1(392, 6);
    qkv_gemm<<<g1, 128, GSMEM>>>();

    attn_hmma<<<16 * 6 * 64, 128>>>(pe);

    dim3 g3(392, 2);
    proj_gemm<<<g3, 128, GSMEM>>>(bout, out);
}

// round 10
// speedup vs baseline: 1.1856x; 1.0891x over previous
#include <cuda_runtime.h>
#include <cuda_fp16.h>
#include <cstdint>

#define QT (16*6*64*49*32)            // 9,633,792 elements per q/k/v tensor

// K-dimension tensors use pair-interleaved layout within each 16-half k-group:
// orig pair q (halves 2q,2q+1) stored at pair ((q&3)<<1)|(q>>2).
__device__ __half g_xh[50176 * 192];  // rolled x, fp16, permuted-k
__device__ __half g_wh[576 * 192];    // wqkv^T [n][k] fp16, permuted-k
__device__ __half g_woh[192 * 192];   // wout^T [n][k] fp16, permuted-k
__device__ __half g_qkvh[3u * QT];    // q|k|v fp16, window layout (q pre-scaled)
__device__ __half g_atth[QT];         // attention out fp16, window layout, permuted-k
__device__ float  g_bias[4 * 4096];   // bias+mask tables [type][i*64+j], pad=-1e9

// ---------------- helpers ----------------
__device__ __forceinline__ void mma16(float* c, const uint32_t* a, const uint32_t* b) {
    asm volatile("mma.sync.aligned.m16n8k16.row.col.f32.f16.f16.f32 "
        "{%0,%1,%2,%3}, {%4,%5,%6,%7}, {%8,%9}, {%0,%1,%2,%3};\n"
        : "+f"(c[0]), "+f"(c[1]), "+f"(c[2]), "+f"(c[3])
        : "r"(a[0]), "r"(a[1]), "r"(a[2]), "r"(a[3]), "r"(b[0]), "r"(b[1]));
}
__device__ __forceinline__ void ldsm4t(uint32_t* r, uint32_t addr) {
    asm volatile("ldmatrix.sync.aligned.m8n8.x4.trans.shared.b16 {%0,%1,%2,%3}, [%4];"
        : "=r"(r[0]), "=r"(r[1]), "=r"(r[2]), "=r"(r[3]) : "r"(addr));
}
__device__ __forceinline__ void cpa16(uint32_t s, const void* g) {
    asm volatile("cp.async.cg.shared.global [%0], [%1], 16;" :: "r"(s), "l"(g));
}
#define CP_COMMIT() asm volatile("cp.async.commit_group;")
#define CP_WAIT2()  asm volatile("cp.async.wait_group 2;")
#define CP_WAIT1()  asm volatile("cp.async.wait_group 1;")
#define CP_WAIT0()  asm volatile("cp.async.wait_group 0;")
__device__ __forceinline__ uint32_t smem_u32(const void* p) {
    uint32_t a;
    asm("{ .reg .u64 t; cvta.to.shared.u64 t, %1; cvt.u32.u64 %0, t; }" : "=r"(a) : "l"(p));
    return a;
}
__device__ __forceinline__ uint32_t h2u(__half2 h) { return *reinterpret_cast<uint32_t*>(&h); }

// ================= prep kernels =================
__global__ __launch_bounds__(256) void prep_x(const float* __restrict__ x) {
    int i = blockIdx.x * 256 + threadIdx.x;
    int e = i * 4;
    int t = e / 192, c = e - t * 192;
    int b = t / 3136; int r = t - b * 3136;
    int y = r / 56, xx = r - y * 56;
    int ys = y + 3;  if (ys >= 56) ys -= 56;
    int xs = xx + 3; if (xs >= 56) xs -= 56;
    float4 v = *(const float4*)(x + ((b * 56 + ys) * 56 + xs) * 192 + c);
    int gb = e & ~15;
    int q = (e >> 1) & 7;
    int p0 = ((q & 3) << 1) | (q >> 2);
    int q1 = q + 1;
    int p1 = ((q1 & 3) << 1) | (q1 >> 2);
    *(__half2*)(g_xh + gb + 2 * p0) = __floats2half2_rn(v.x, v.y);
    *(__half2*)(g_xh + gb + 2 * p1) = __floats2half2_rn(v.z, v.w);
}
__global__ __launch_bounds__(256) void prep_wb(const float* __restrict__ w,
                                               const float* __restrict__ wo) {
    int i = blockIdx.x * 256 + threadIdx.x;
    int e = i * 4;
    __half* dst;
    float vv[4];
    if (e < 110592) {
        int n = e / 192, k = e - n * 192;
#pragma unroll
        for (int j = 0; j < 4; j++) vv[j] = w[(k + j) * 576 + n];
        dst = g_wh;
    } else {
        int e2 = e - 110592;
        int n = e2 / 192, k = e2 - n * 192;
#pragma unroll
        for (int j = 0; j < 4; j++) vv[j] = wo[(k + j) * 192 + n];
        dst = g_woh - 110592;
    }
    int gb = e & ~15;
    int q = (e >> 1) & 7;
    int p0 = ((q & 3) << 1) | (q >> 2);
    int q1 = q + 1;
    int p1 = ((q1 & 3) << 1) | (q1 >> 2);
    *(__half2*)(dst + gb + 2 * p0) = __floats2half2_rn(vv[0], vv[1]);
    *(__half2*)(dst + gb + 2 * p1) = __floats2half2_rn(vv[2], vv[3]);
}
__global__ __launch_bounds__(256) void prep_bias(const float* __restrict__ pe) {
    int idx = blockIdx.x * 256 + threadIdx.x;       // 16384
    int type = idx >> 12, r = idx & 4095;
    int i = r >> 6, j = r & 63;
    float v = -1e9f;
    if (i < 49 && j < 49) {
        int iy = i / 7, ix = i - iy * 7;
        int jy = j / 7, jx = j - jy * 7;
        v = pe[(jy - iy + 6) * 13 + (jx - ix + 6)];
        if ((type & 2) && ((iy >= 4) != (jy >= 4))) v -= 1e9f;
        if ((type & 1) && ((ix >= 4) != (jx >= 4))) v -= 1e9f;
    }
    g_bias[idx] = v;
}

// ============ fp16 GEMM: BM=128, BN=96, BK=32, 128 threads, 3-stage, LDA=48 ============
#define LDA 48
#define A_ST (128 * LDA)
#define B_ST (96 * LDA)
#define STAGE (A_ST + B_ST)
#define GSMEM (3 * STAGE * 2)        // 64512 B dynamic

// ================= Kernel 1: QKV GEMM =================
__global__ __launch_bounds__(128, 3) void qkv_gemm(void)
{
    extern __shared__ __align__(16) __half sm[];

    const int tid  = threadIdx.x;
    const int warp = tid >> 5, lane = tid & 31;
    const int wm   = warp & 1, wn = warp >> 1;
    const int g    = lane >> 2, tg = lane & 3;
    const int bm   = blockIdx.x * 128;
    const int nb   = blockIdx.y;

    const __half* ap = g_xh + (size_t)(bm + tid) * 192;
    const int bn = tid >> 2, bq = tid & 3;
    const uint32_t smb = smem_u32(sm);

#define LD_CHUNK(cc, ss) do { \
        uint32_t ad = smb + (uint32_t)((ss) * STAGE + tid * LDA) * 2; \
        const __half* asrc = ap + (cc) * 32; \
        cpa16(ad + 0,  asrc + 0);  cpa16(ad + 16, asrc + 8); \
        cpa16(ad + 32, asrc + 16); cpa16(ad + 48, asrc + 24); \
        uint32_t bd = smb + (uint32_t)((ss) * STAGE + A_ST) * 2; \
        _Pragma("unroll") \
        for (int ii = 0; ii < 3; ii++) { \
            int n = bn + ii * 32; \
            cpa16(bd + (uint32_t)(n * LDA + bq * 8) * 2, \
                  g_wh + (size_t)(nb * 96 + n) * 192 + (cc) * 32 + bq * 8); \
        } \
        CP_COMMIT(); } while (0)

    float c[4][6][4] = {};
    LD_CHUNK(0, 0);
    LD_CHUNK(1, 1);

    int st = 0;
#pragma unroll 1
    for (int ch = 0; ch < 6; ch++) {
        __syncthreads();
        if (ch < 4) {
            int s2 = st + 2; if (s2 >= 3) s2 -= 3;
            LD_CHUNK(ch + 2, s2);
        }
        if (ch < 4)       CP_WAIT2();
        else if (ch == 4) CP_WAIT1();
        else              CP_WAIT0();
        __syncthreads();

        const __half* Ab = sm + st * STAGE;
        const __half* Bb = Ab + A_ST;
#pragma unroll
        for (int kk = 0; kk < 32; kk += 16) {
            uint32_t af[4][4], bf[6][2];
#pragma unroll
            for (int mi = 0; mi < 4; mi++) {
                const int rb = wm * 64 + mi * 16 + g;
                uint2 v0 = *(const uint2*)(Ab + rb * LDA + kk + 4 * tg);
                uint2 v1 = *(const uint2*)(Ab + (rb + 8) * LDA + kk + 4 * tg);
                af[mi][0] = v0.x; af[mi][2] = v0.y;
                af[mi][1] = v1.x; af[mi][3] = v1.y;
            }
#pragma unroll
            for (int ni = 0; ni < 6; ni++) {
                uint2 vb = *(const uint2*)(Bb + (wn * 48 + ni * 8 + g) * LDA + kk + 4 * tg);
                bf[ni][0] = vb.x; bf[ni][1] = vb.y;
            }
#pragma unroll
            for (int mi = 0; mi < 4; mi++)
#pragma unroll
                for (int ni = 0; ni < 6; ni++)
                    mma16(c[mi][ni], af[mi], bf[ni]);
        }
        st++; if (st == 3) st = 0;
    }

    // epilogue: scatter into window layout; q pre-scaled by 1/sqrt(32)
    const int t = nb >> 1;
    const float smul = (t == 0) ? 0.17677669529663687f : 1.0f;
    __half* qb = g_qkvh + (size_t)t * QT;
#pragma unroll
    for (int mi = 0; mi < 4; mi++) {
#pragma unroll
        for (int half = 0; half < 2; half++) {
            int r = bm + wm * 64 + mi * 16 + g + half * 8;
            int b = r / 3136; int rr = r - b * 3136;
            int y = rr / 56, xx = rr - y * 56;
            int wv = (y / 7) * 8 + (xx / 7);
            int tk = (y % 7) * 7 + (xx % 7);
            __half* base = qb + b * 602112 + wv * 1568 + tk * 32;
#pragma unroll
            for (int ni = 0; ni < 6; ni++) {
                int cp = nb * 96 + wn * 48 + ni * 8 + tg * 2;
                int cc = cp - t * 192;
                int h = cc >> 5, d = cc & 31;
                *(__half2*)(base + h * 100352 + d) =
                    __floats2half2_rn(c[mi][ni][half * 2] * smul,
                                      c[mi][ni][half * 2 + 1] * smul);
            }
        }
    }
}

// ================= Kernel 2: HMMA attention (ldsm-trans PV, bias table) =================
#define LDQ 40

__global__ __launch_bounds__(128) void attn_hmma(void)
{
    __shared__ __align__(16) __half Qs[64 * LDQ];
    __shared__ __align__(16) __half Ks[64 * LDQ];
    __shared__ __align__(16) __half Vs[64 * LDQ];

    const int tid = threadIdx.x;
    const int w = tid >> 5, lane = tid & 31;
    const int g = lane >> 2, t = lane & 3;
    const int bx = blockIdx.x;
    const int wv = bx & 63;
    const int wtype = ((wv >> 3) == 7 ? 2 : 0) | ((wv & 7) == 7 ? 1 : 0);
    const float* bias = g_bias + wtype * 4096;

    const __half2* qg = (const __half2*)(g_qkvh + (size_t)bx * 1568);
    const __half2* kg = (const __half2*)(g_qkvh + (size_t)QT + (size_t)bx * 1568);
    const __half2* vg = (const __half2*)(g_qkvh + 2 * (size_t)QT + (size_t)bx * 1568);

    const __half2 z2 = __floats2half2_rn(0.f, 0.f);
    for (int p = tid; p < 1024; p += 128) {
        int i = p >> 4, dp = p & 15;
        __half2 qv = z2, kv = z2, vv = z2;
        if (i < 49) { qv = qg[p]; kv = kg[p]; vv = vg[p]; }
        *(__half2*)(Qs + i * LDQ + dp * 2) = qv;
        *(__half2*)(Ks + i * LDQ + dp * 2) = kv;
        *(__half2*)(Vs + i * LDQ + dp * 2) = vv;
    }
    __syncthreads();

    // ---- S = (Q*scale) K^T ----
    float S[8][4] = {};
    const __half* qrow = Qs + (w * 16 + g) * LDQ;
#pragma unroll
    for (int kk = 0; kk < 32; kk += 16) {
        uint32_t a[4];
        a[0] = *(const uint32_t*)(qrow + kk + 2 * t);
        a[1] = *(const uint32_t*)(qrow + 8 * LDQ + kk + 2 * t);
        a[2] = *(const uint32_t*)(qrow + kk + 8 + 2 * t);
        a[3] = *(const uint32_t*)(qrow + 8 * LDQ + kk + 8 + 2 * t);
#pragma unroll
        for (int n = 0; n < 8; n++) {
            uint32_t b[2];
            const __half* kb = Ks + (n * 8 + g) * LDQ + kk + 2 * t;
            b[0] = *(const uint32_t*)(kb);
            b[1] = *(const uint32_t*)(kb + 8);
            mma16(S[n], a, b);
        }
    }

    // ---- bias + softmax (table lookups, no div/branch) ----
#pragma unroll
    for (int rw = 0; rw < 2; rw++) {
        int i = w * 16 + g + rw * 8;
        const float* brow = bias + i * 64 + 2 * t;
        float mx = -1e30f;
#pragma unroll
        for (int n = 0; n < 8; n++) {
            float2 bb = *(const float2*)(brow + n * 8);
            float v0 = S[n][rw * 2]     + bb.x;
            float v1 = S[n][rw * 2 + 1] + bb.y;
            S[n][rw * 2]     = v0;
            S[n][rw * 2 + 1] = v1;
            mx = fmaxf(mx, fmaxf(v0, v1));
        }
        mx = fmaxf(mx, __shfl_xor_sync(0xffffffffu, mx, 1));
        mx = fmaxf(mx, __shfl_xor_sync(0xffffffffu, mx, 2));
        float sm = 0.f;
#pragma unroll
        for (int n = 0; n < 8; n++) {
#pragma unroll
            for (int e = 0; e < 2; e++) {
                float ex = __expf(S[n][rw * 2 + e] - mx);
                S[n][rw * 2 + e] = ex;
                sm += ex;
            }
        }
        sm += __shfl_xor_sync(0xffffffffu, sm, 1);
        sm += __shfl_xor_sync(0xffffffffu, sm, 2);
        float inv = 1.f / sm;
#pragma unroll
        for (int n = 0; n < 8; n++) {
            S[n][rw * 2 + 0] *= inv;
            S[n][rw * 2 + 1] *= inv;
        }
    }

    // ---- repack P into A-fragments ----
    uint32_t Pa[4][4];
#pragma unroll
    for (int c = 0; c < 4; c++) {
        Pa[c][0] = h2u(__floats2half2_rn(S[2 * c][0],     S[2 * c][1]));
        Pa[c][1] = h2u(__floats2half2_rn(S[2 * c][2],     S[2 * c][3]));
        Pa[c][2] = h2u(__floats2half2_rn(S[2 * c + 1][0], S[2 * c + 1][1]));
        Pa[c][3] = h2u(__floats2half2_rn(S[2 * c + 1][2], S[2 * c + 1][3]));
    }

    // ---- O = P V  (B-fragments via ldmatrix.trans on natural V) ----
    const uint32_t vs_b = smem_u32(Vs);
    const int lr = lane & 7, lm = (lane >> 3) & 1, lk = lane >> 4;
    float O[4][4] = {};
#pragma unroll
    for (int c = 0; c < 4; c++) {
#pragma unroll
        for (int nh = 0; nh < 2; nh++) {
            uint32_t r[4];
            ldsm4t(r, vs_b + (uint32_t)((c * 16 + lr + lm * 8) * LDQ + nh * 16 + lk * 8) * 2);
            uint32_t b0[2] = { r[0], r[1] };
            uint32_t b1[2] = { r[2], r[3] };
            mma16(O[nh * 2],     Pa[c], b0);
            mma16(O[nh * 2 + 1], Pa[c], b1);
        }
    }

    // ---- store fp16, permuted-k layout ----
    __half* og = g_atth + (size_t)bx * 1568;
#pragma unroll
    for (int rw = 0; rw < 2; rw++) {
        int i = w * 16 + g + rw * 8;
        if (i < 49) {
#pragma unroll
            for (int nt = 0; nt < 4; nt++) {
                int h = nt * 8 + 2 * t;
                int b16 = h & 16;
                int q = (h >> 1) & 7;
                int pp = ((q & 3) << 1) | (q >> 2);
                *(__half2*)(og + i * 32 + b16 + 2 * pp) =
                    __floats2half2_rn(O[nt][rw * 2], O[nt][rw * 2 + 1]);
            }
        }
    }
}

// ================= Kernel 3: out-proj GEMM + inverse roll (3-stage, LDA=48) =================
__global__ __launch_bounds__(128, 3) void proj_gemm(
    const float* __restrict__ bout, float* __restrict__ out)
{
    extern __shared__ __align__(16) __half sm[];

    const int tid  = threadIdx.x;
    const int warp = tid >> 5, lane = tid & 31;
    const int wm   = warp & 1, wn = warp >> 1;
    const int g    = lane >> 2, tg = lane & 3;
    const int bm   = blockIdx.x * 128;
    const int nb   = blockIdx.y;

    const __half* abase;
    {
        int row = bm + tid;
        int b = row / 3136; int r = row - b * 3136;
        int y = r / 56, xx = r - y * 56;
        int wv = (y / 7) * 8 + (xx / 7);
        int tk = (y % 7) * 7 + (xx % 7);
        abase = g_atth + b * 602112 + wv * 1568 + tk * 32;
    }
    const int bn = tid >> 2, bq = tid & 3;
    const uint32_t smb = smem_u32(sm);

#define LD_CHUNK_P(cc, ss) do { \
        uint32_t ad = smb + (uint32_t)((ss) * STAGE + tid * LDA) * 2; \
        const __half* asrc = abase + (cc) * 100352; \
        cpa16(ad + 0,  asrc + 0);  cpa16(ad + 16, asrc + 8); \
        cpa16(ad + 32, asrc + 16); cpa16(ad + 48, asrc + 24); \
        uint32_t bd = smb + (uint32_t)((ss) * STAGE + A_ST) * 2; \
        _Pragma("unroll") \
        for (int ii = 0; ii < 3; ii++) { \
            int n = bn + ii * 32; \
            cpa16(bd + (uint32_t)(n * LDA + bq * 8) * 2, \
                  g_woh + (size_t)(nb * 96 + n) * 192 + (cc) * 32 + bq * 8); \
        } \
        CP_COMMIT(); } while (0)

    float c[4][6][4] = {};
    LD_CHUNK_P(0, 0);
    LD_CHUNK_P(1, 1);

    int st = 0;
#pragma unroll 1
    for (int ch = 0; ch < 6; ch++) {
        __syncthreads();
        if (ch < 4) {
            int s2 = st + 2; if (s2 >= 3) s2 -= 3;
            LD_CHUNK_P(ch + 2, s2);
        }
        if (ch < 4)       CP_WAIT2();
        else if (ch == 4) CP_WAIT1();
        else              CP_WAIT0();
        __syncthreads();

        const __half* Ab = sm + st * STAGE;
        const __half* Bb = Ab + A_ST;
#pragma unroll
        for (int kk = 0; kk < 32; kk += 16) {
            uint32_t af[4][4], bf[6][2];
#pragma unroll
            for (int mi = 0; mi < 4; mi++) {
                const int rb = wm * 64 + mi * 16 + g;
                uint2 v0 = *(const uint2*)(Ab + rb * LDA + kk + 4 * tg);
                uint2 v1 = *(const uint2*)(Ab + (rb + 8) * LDA + kk + 4 * tg);
                af[mi][0] = v0.x; af[mi][2] = v0.y;
                af[mi][1] = v1.x; af[mi][3] = v1.y;
            }
#pragma unroll
            for (int ni = 0; ni < 6; ni++) {
                uint2 vb = *(const uint2*)(Bb + (wn * 48 + ni * 8 + g) * LDA + kk + 4 * tg);
                bf[ni][0] = vb.x; bf[ni][1] = vb.y;
            }
#pragma unroll
            for (int mi = 0; mi < 4; mi++)
#pragma unroll
                for (int ni = 0; ni < 6; ni++)
                    mma16(c[mi][ni], af[mi], bf[ni]);
        }
        st++; if (st == 3) st = 0;
    }

#pragma unroll
    for (int mi = 0; mi < 4; mi++) {
#pragma unroll
        for (int half = 0; half < 2; half++) {
            int r = bm + wm * 64 + mi * 16 + g + half * 8;
            int b = r / 3136; int rr = r - b * 3136;
            int y = rr / 56, xx = rr - y * 56;
            int yo = y + 3;  if (yo >= 56) yo -= 56;
            int xo = xx + 3; if (xo >= 56) xo -= 56;
            float* op = out + ((b * 56 + yo) * 56 + xo) * 192;
#pragma unroll
            for (int ni = 0; ni < 6; ni++) {
                int cp = nb * 96 + wn * 48 + ni * 8 + tg * 2;
                float2 bb = *(const float2*)(bout + cp);
                float2 v = make_float2(c[mi][ni][half * 2] + bb.x,
                                       c[mi][ni][half * 2 + 1] + bb.y);
                *(float2*)(op + cp) = v;
            }
        }
    }
}

// ================= launch =================
extern "C" void kernel_launch(void* const* d_in, const int* in_sizes, int n_in,
                              void* d_out, int out_size)
{
    const float* x    = (const float*)d_in[0];
    const float* wqkv = (const float*)d_in[1];
    const float* pe   = (const float*)d_in[2];
    const float* wout = (const float*)d_in[3];
    const float* bout = (const float*)d_in[4];
    float* out = (float*)d_out;

    static int configured = 0;
    if (!configured) {
        cudaFuncSetAttribute(qkv_gemm, cudaFuncAttributeMaxDynamicSharedMemorySize, GSMEM);
        cudaFuncSetAttribute(proj_gemm, cudaFuncAttributeMaxDynamicSharedMemorySize, GSMEM);
        configured = 1;
    }

    prep_x<<<9408, 256>>>(x);
    prep_wb<<<144, 256>>>(wqkv, wout);
    prep_bias<<<64, 256>>>(pe);

    dim3 g1(392, 6);
    qkv_gemm<<<g1, 128, GSMEM>>>();

    attn_hmma<<<16 * 6 * 64, 128>>>();

    dim3 g3(392, 2);
    proj_gemm<<<g3, 128, GSMEM>>>(bout, out);
}